// round 9
// baseline (speedup 1.0000x reference)
#include <cuda_runtime.h>
#include <cuda_bf16.h>

#define T_DIM 512
#define B_DIM 512
#define FDIM  64
#define H_DIM 128
#define G3    384   // 3*H
#define BSTRIDE ((size_t)T_DIM * G3)

// ---- scratch (device globals; no allocation) ----
__device__ float g_xw[(size_t)B_DIM * T_DIM * G3];   // x@Wx + b_in per (b,t)

typedef unsigned long long ull;

// packed f32x2 ops
__device__ __forceinline__ void ffma2(ull& d, ull a, ull b) {
    asm("fma.rn.f32x2 %0, %1, %2, %3;" : "=l"(d) : "l"(a), "l"(b), "l"(d));
}
__device__ __forceinline__ ull fadd2(ull a, ull b) {
    ull d;
    asm("add.rn.f32x2 %0, %1, %2;" : "=l"(d) : "l"(a), "l"(b));
    return d;
}
__device__ __forceinline__ ull packf2(float lo, float hi) {
    ull u;
    asm("mov.b64 %0, {%1,%2};" : "=l"(u) : "f"(lo), "f"(hi));
    return u;
}
__device__ __forceinline__ float ull_hsum(ull u) {
    float lo, hi;
    asm("mov.b64 {%0,%1}, %2;" : "=f"(lo), "=f"(hi) : "l"(u));
    return lo + hi;
}
__device__ __forceinline__ float fsigmoid(float x) {
    return __fdividef(1.f, 1.f + __expf(-x));
}
__device__ __forceinline__ float ftanh(float x) {
    float e = __expf(2.f * x);
    return 1.f - __fdividef(2.f, e + 1.f);
}

// ---------------------------------------------------------------------------
// Kernel 1: xw = x @ Wx + b_in as a register-tiled GEMM.
// 4096 blocks x 768 threads; block tile 64 rows x 384 cols; thread tile
// 4 rows x 8 cols (32 acc regs). Wx (96 KB) and x^T (17 KB) staged in smem:
// per k only 3 LDS.128 + 16 FFMA2 per thread -> FMA-bound, 6 warps/SMSP.
// ---------------------------------------------------------------------------
#define XW_NTH 768
#define XT_PAD 68
#define XW_SMEM_FLOATS (FDIM * G3 + FDIM * XT_PAD)   // ws + xT
extern __shared__ float smx[];

__global__ void __launch_bounds__(XW_NTH, 1) xw_kernel(const float* __restrict__ inputs,
                                                       const float* __restrict__ Wx,
                                                       const float* __restrict__ bias) {
    float* ws = smx;                       // [64][384]
    float* xT = smx + FDIM * G3;           // [64][XT_PAD]
    const int row0 = blockIdx.x * 64;
    const int t  = threadIdx.x;
    const int rg = t & 15;                 // row group: rows 4rg..4rg+3
    const int cg = t >> 4;                 // col group: cols 8cg..8cg+7

    // stage Wx (layout identical -> linear copy) and x^T
    for (int i = t; i < FDIM * G3; i += XW_NTH) ws[i] = Wx[i];
    for (int i = t; i < 64 * FDIM; i += XW_NTH) {
        int r = i >> 6, k = i & 63;
        xT[k * XT_PAD + r] = inputs[(size_t)(row0 + r) * 65 + k];
    }
    // bias pairs for this thread's 8 cols
    ull bp[4];
    #pragma unroll
    for (int m = 0; m < 4; m++)
        bp[m] = packf2(bias[8 * cg + 2 * m], bias[8 * cg + 2 * m + 1]);
    __syncthreads();

    ull acc[4][4];   // [row][col-pair]
    #pragma unroll
    for (int r = 0; r < 4; r++)
        #pragma unroll
        for (int m = 0; m < 4; m++) acc[r][m] = 0ull;

    #pragma unroll 8
    for (int k = 0; k < FDIM; k++) {
        float4 xv = *reinterpret_cast<const float4*>(&xT[k * XT_PAD + 4 * rg]);
        ull xd0 = packf2(xv.x, xv.x);
        ull xd1 = packf2(xv.y, xv.y);
        ull xd2 = packf2(xv.z, xv.z);
        ull xd3 = packf2(xv.w, xv.w);
        ulonglong2 w01 = *reinterpret_cast<const ulonglong2*>(&ws[k * G3 + 8 * cg]);
        ulonglong2 w23 = *reinterpret_cast<const ulonglong2*>(&ws[k * G3 + 8 * cg + 4]);
        ffma2(acc[0][0], xd0, w01.x); ffma2(acc[0][1], xd0, w01.y);
        ffma2(acc[0][2], xd0, w23.x); ffma2(acc[0][3], xd0, w23.y);
        ffma2(acc[1][0], xd1, w01.x); ffma2(acc[1][1], xd1, w01.y);
        ffma2(acc[1][2], xd1, w23.x); ffma2(acc[1][3], xd1, w23.y);
        ffma2(acc[2][0], xd2, w01.x); ffma2(acc[2][1], xd2, w01.y);
        ffma2(acc[2][2], xd2, w23.x); ffma2(acc[2][3], xd2, w23.y);
        ffma2(acc[3][0], xd3, w01.x); ffma2(acc[3][1], xd3, w01.y);
        ffma2(acc[3][2], xd3, w23.x); ffma2(acc[3][3], xd3, w23.y);
    }

    #pragma unroll
    for (int r = 0; r < 4; r++) {
        float* dst = &g_xw[(size_t)(row0 + 4 * rg + r) * G3 + 8 * cg];
        ulonglong2 v;
        v.x = fadd2(acc[r][0], bp[0]);
        v.y = fadd2(acc[r][1], bp[1]);
        *reinterpret_cast<ulonglong2*>(dst) = v;
        v.x = fadd2(acc[r][2], bp[2]);
        v.y = fadd2(acc[r][3], bp[3]);
        *reinterpret_cast<ulonglong2*>(dst + 4) = v;
    }
}

// ---------------------------------------------------------------------------
// Kernel 2: GRU scan + fused head. 128 blocks x 512 threads, 4 batches/block.
// k-QUARTER x 3-col split: warp w covers k in [32*(w&3), +32); lane owns cols
// {c0, c0+32, c0+64} with c0 = (w>>2)*96 + lane. Cols c0, c0+32 weights in
// registers (32 ull); col c0+64 weights streamed from 64 KB smem. 16 warps
// (4/SMSP) + ~115 regs -> latency-hiding headroom vs round 8's 12 warps @168.
// Partials in gq[4][4][384]; activation = exactly 1 unit/thread.
// ---------------------------------------------------------------------------
#define SCAN_NTH 512
#define WSM_BYTES (16 * SCAN_NTH * 8)   // 64 KB of ull

__global__ void __launch_bounds__(SCAN_NTH, 1) gru_scan_kernel(
        const float* __restrict__ inputs,
        const float* __restrict__ Wh,
        const float* __restrict__ bias,
        const float* __restrict__ W_state,
        const float* __restrict__ w1,
        const float* __restrict__ b1v,
        const float* __restrict__ gamma,
        const float* __restrict__ beta,
        const float* __restrict__ mean,
        const float* __restrict__ var,
        const float* __restrict__ w2,
        const float* __restrict__ b2,
        float* __restrict__ out) {
    __shared__ __align__(16) float hs[4][H_DIM];    // 2 KB
    __shared__ float gq[4][4][G3];                  // 24 KB partials [kq][b][col]
    __shared__ float red[4][64];
    extern __shared__ ull wsm[];                    // [16][SCAN_NTH] col-C weights

    const int t    = threadIdx.x;
    const int w    = t >> 5;
    const int lane = t & 31;
    const int kq   = w & 3;
    const int kb   = kq * 32;
    const int c0   = (w >> 2) * 96 + lane;          // cols c0, c0+32, c0+64
    const int b0   = blockIdx.x * 4;

    // activation role: one (ab, j) per thread
    const int j  = t & 127;
    const int ab = t >> 7;
    const float brz = bias[G3 + j];
    const float brr = bias[G3 + 128 + j];
    const float brh = bias[G3 + 256 + j];

    // weights: cols A, B in regs; col C into smem
    ull wA[16], wB[16];
    #pragma unroll
    for (int i = 0; i < 16; i++) {
        const float* p0 = &Wh[(kb + 2 * i) * G3];
        const float* p1 = &Wh[(kb + 2 * i + 1) * G3];
        wA[i] = packf2(__ldg(&p0[c0]),      __ldg(&p1[c0]));
        wB[i] = packf2(__ldg(&p0[c0 + 32]), __ldg(&p1[c0 + 32]));
        wsm[i * SCAN_NTH + t] = packf2(__ldg(&p0[c0 + 64]), __ldg(&p1[c0 + 64]));
    }

    (&hs[0][0])[t] = 0.f;
    const float* __restrict__ xwp = g_xw + (size_t)(b0 + ab) * BSTRIDE + j;
    __syncthreads();

    for (int step = 0; step < T_DIM; step++) {
        const size_t so = (size_t)step * G3;
        // prefetch input preacts for this thread's activation unit
        float xz = xwp[so], xr = xwp[so + 128], xh = xwp[so + 256];

        ull aA0 = 0ull, aA1 = 0ull, aA2 = 0ull, aA3 = 0ull;
        ull aB0 = 0ull, aB1 = 0ull, aB2 = 0ull, aB3 = 0ull;
        ull aC0 = 0ull, aC1 = 0ull, aC2 = 0ull, aC3 = 0ull;

        #pragma unroll
        for (int k4 = 0; k4 < 8; k4++) {
            const int k = kb + 4 * k4;
            ull wc0 = wsm[(2 * k4) * SCAN_NTH + t];
            ull wc1 = wsm[(2 * k4 + 1) * SCAN_NTH + t];
            ulonglong2 h0 = *reinterpret_cast<const ulonglong2*>(&hs[0][k]);
            ffma2(aA0, wA[2 * k4], h0.x); ffma2(aA0, wA[2 * k4 + 1], h0.y);
            ffma2(aB0, wB[2 * k4], h0.x); ffma2(aB0, wB[2 * k4 + 1], h0.y);
            ffma2(aC0, wc0, h0.x);        ffma2(aC0, wc1, h0.y);
            ulonglong2 h1 = *reinterpret_cast<const ulonglong2*>(&hs[1][k]);
            ffma2(aA1, wA[2 * k4], h1.x); ffma2(aA1, wA[2 * k4 + 1], h1.y);
            ffma2(aB1, wB[2 * k4], h1.x); ffma2(aB1, wB[2 * k4 + 1], h1.y);
            ffma2(aC1, wc0, h1.x);        ffma2(aC1, wc1, h1.y);
            ulonglong2 h2 = *reinterpret_cast<const ulonglong2*>(&hs[2][k]);
            ffma2(aA2, wA[2 * k4], h2.x); ffma2(aA2, wA[2 * k4 + 1], h2.y);
            ffma2(aB2, wB[2 * k4], h2.x); ffma2(aB2, wB[2 * k4 + 1], h2.y);
            ffma2(aC2, wc0, h2.x);        ffma2(aC2, wc1, h2.y);
            ulonglong2 h3 = *reinterpret_cast<const ulonglong2*>(&hs[3][k]);
            ffma2(aA3, wA[2 * k4], h3.x); ffma2(aA3, wA[2 * k4 + 1], h3.y);
            ffma2(aB3, wB[2 * k4], h3.x); ffma2(aB3, wB[2 * k4 + 1], h3.y);
            ffma2(aC3, wc0, h3.x);        ffma2(aC3, wc1, h3.y);
        }

        gq[kq][0][c0]      = ull_hsum(aA0);
        gq[kq][0][c0 + 32] = ull_hsum(aB0);
        gq[kq][0][c0 + 64] = ull_hsum(aC0);
        gq[kq][1][c0]      = ull_hsum(aA1);
        gq[kq][1][c0 + 32] = ull_hsum(aB1);
        gq[kq][1][c0 + 64] = ull_hsum(aC1);
        gq[kq][2][c0]      = ull_hsum(aA2);
        gq[kq][2][c0 + 32] = ull_hsum(aB2);
        gq[kq][2][c0 + 64] = ull_hsum(aC2);
        gq[kq][3][c0]      = ull_hsum(aA3);
        gq[kq][3][c0 + 32] = ull_hsum(aB3);
        gq[kq][3][c0 + 64] = ull_hsum(aC3);
        __syncthreads();

        // activation: this thread's (ab, j)
        {
            float pz = gq[0][ab][j]       + gq[1][ab][j]       + gq[2][ab][j]       + gq[3][ab][j];
            float pr = gq[0][ab][128 + j] + gq[1][ab][128 + j] + gq[2][ab][128 + j] + gq[3][ab][128 + j];
            float ph = gq[0][ab][256 + j] + gq[1][ab][256 + j] + gq[2][ab][256 + j] + gq[3][ab][256 + j];
            float z  = fsigmoid(xz + pz + brz);
            float r  = fsigmoid(xr + pr + brr);
            float hh = ftanh(xh + r * (ph + brh));
            hs[ab][j] = z * hs[ab][j] + (1.f - z) * hh;
        }
        __syncthreads();
    }

    // ---- fused head: hidden += W_state[idx]; out = BN(relu(hid@w1+b1)) @ w2 + b2
    {
        float st = inputs[((size_t)(b0 + ab) * T_DIM + (T_DIM - 1)) * 65 + 64];
        int idx = (int)st;
        idx = idx < 0 ? 0 : (idx > 2 ? 2 : idx);
        gq[0][ab][j] = hs[ab][j] + W_state[idx * H_DIM + j];
    }
    __syncthreads();

    if (t < 256) {
        int bb = t >> 6, tt = t & 63;
        float a = b1v[tt];
        #pragma unroll 8
        for (int k = 0; k < H_DIM; k++)
            a = fmaf(gq[0][bb][k], w1[k * 64 + tt], a);
        a = fmaxf(a, 0.f);
        a = (a - mean[tt]) * rsqrtf(var[tt] + 1e-3f) * gamma[tt] + beta[tt];
        red[bb][tt] = a * w2[tt];
    }
    __syncthreads();

    if (t < 4) {
        float s = b2[0];
        #pragma unroll 8
        for (int k = 0; k < 64; k++) s += red[t][k];
        out[b0 + t] = s;
    }
}

// ---------------------------------------------------------------------------
extern "C" void kernel_launch(void* const* d_in, const int* in_sizes, int n_in,
                              void* d_out, int out_size) {
    const float* inputs  = (const float*)d_in[0];
    const float* Wx      = (const float*)d_in[1];
    const float* Wh      = (const float*)d_in[2];
    const float* bias    = (const float*)d_in[3];
    const float* W_state = (const float*)d_in[4];
    const float* w1      = (const float*)d_in[5];
    const float* b1      = (const float*)d_in[6];
    const float* gamma   = (const float*)d_in[7];
    const float* beta    = (const float*)d_in[8];
    const float* mean    = (const float*)d_in[9];
    const float* var     = (const float*)d_in[10];
    const float* w2      = (const float*)d_in[11];
    const float* b2      = (const float*)d_in[12];
    float* out = (float*)d_out;

    static int attr_done = 0;
    if (!attr_done) {
        cudaFuncSetAttribute(xw_kernel,
                             cudaFuncAttributeMaxDynamicSharedMemorySize,
                             XW_SMEM_FLOATS * 4);
        cudaFuncSetAttribute(gru_scan_kernel,
                             cudaFuncAttributeMaxDynamicSharedMemorySize,
                             WSM_BYTES);
        attr_done = 1;
    }

    xw_kernel<<<(B_DIM * T_DIM) / 64, XW_NTH, XW_SMEM_FLOATS * 4>>>(inputs, Wx, bias);
    gru_scan_kernel<<<B_DIM / 4, SCAN_NTH, WSM_BYTES>>>(
        inputs, Wh, bias, W_state, w1, b1,
        gamma, beta, mean, var, w2, b2, out);
}

// round 10
// speedup vs baseline: 1.0352x; 1.0352x over previous
#include <cuda_runtime.h>
#include <cuda_bf16.h>

#define T_DIM 512
#define B_DIM 512
#define FDIM  64
#define H_DIM 128
#define G3    384   // 3*H
#define BSTRIDE ((size_t)T_DIM * G3)

// ---- scratch (device globals; no allocation) ----
__device__ float g_xw[(size_t)B_DIM * T_DIM * G3];   // x@Wx + b_in per (b,t)

typedef unsigned long long ull;

// packed f32x2 ops
__device__ __forceinline__ void ffma2(ull& d, ull a, ull b) {
    asm("fma.rn.f32x2 %0, %1, %2, %3;" : "=l"(d) : "l"(a), "l"(b), "l"(d));
}
__device__ __forceinline__ ull fadd2(ull a, ull b) {
    ull d;
    asm("add.rn.f32x2 %0, %1, %2;" : "=l"(d) : "l"(a), "l"(b));
    return d;
}
__device__ __forceinline__ ull packf2(float lo, float hi) {
    ull u;
    asm("mov.b64 %0, {%1,%2};" : "=l"(u) : "f"(lo), "f"(hi));
    return u;
}
__device__ __forceinline__ float ull_hsum(ull u) {
    float lo, hi;
    asm("mov.b64 {%0,%1}, %2;" : "=f"(lo), "=f"(hi) : "l"(u));
    return lo + hi;
}
__device__ __forceinline__ float fsigmoid(float x) {
    return __fdividef(1.f, 1.f + __expf(-x));
}
__device__ __forceinline__ float ftanh(float x) {
    float e = __expf(2.f * x);
    return 1.f - __fdividef(2.f, e + 1.f);
}

// ---------------------------------------------------------------------------
// Kernel 1: xw = x @ Wx + b_in as a register-tiled GEMM.  (R9 version, kept)
// 4096 blocks x 768 threads; block tile 64 rows x 384 cols; thread tile
// 4 rows x 8 cols (32 acc regs). Wx (96 KB) and x^T (17 KB) staged in smem:
// per k only 3 LDS.128 + 16 FFMA2 per thread -> FMA-bound, 6 warps/SMSP.
// ---------------------------------------------------------------------------
#define XW_NTH 768
#define XT_PAD 68
#define XW_SMEM_FLOATS (FDIM * G3 + FDIM * XT_PAD)   // ws + xT
extern __shared__ float smx[];

__global__ void __launch_bounds__(XW_NTH, 1) xw_kernel(const float* __restrict__ inputs,
                                                       const float* __restrict__ Wx,
                                                       const float* __restrict__ bias) {
    float* ws = smx;                       // [64][384]
    float* xT = smx + FDIM * G3;           // [64][XT_PAD]
    const int row0 = blockIdx.x * 64;
    const int t  = threadIdx.x;
    const int rg = t & 15;                 // row group: rows 4rg..4rg+3
    const int cg = t >> 4;                 // col group: cols 8cg..8cg+7

    // stage Wx (layout identical -> linear copy) and x^T
    for (int i = t; i < FDIM * G3; i += XW_NTH) ws[i] = Wx[i];
    for (int i = t; i < 64 * FDIM; i += XW_NTH) {
        int r = i >> 6, k = i & 63;
        xT[k * XT_PAD + r] = inputs[(size_t)(row0 + r) * 65 + k];
    }
    // bias pairs for this thread's 8 cols
    ull bp[4];
    #pragma unroll
    for (int m = 0; m < 4; m++)
        bp[m] = packf2(bias[8 * cg + 2 * m], bias[8 * cg + 2 * m + 1]);
    __syncthreads();

    ull acc[4][4];   // [row][col-pair]
    #pragma unroll
    for (int r = 0; r < 4; r++)
        #pragma unroll
        for (int m = 0; m < 4; m++) acc[r][m] = 0ull;

    #pragma unroll 8
    for (int k = 0; k < FDIM; k++) {
        float4 xv = *reinterpret_cast<const float4*>(&xT[k * XT_PAD + 4 * rg]);
        ull xd0 = packf2(xv.x, xv.x);
        ull xd1 = packf2(xv.y, xv.y);
        ull xd2 = packf2(xv.z, xv.z);
        ull xd3 = packf2(xv.w, xv.w);
        ulonglong2 w01 = *reinterpret_cast<const ulonglong2*>(&ws[k * G3 + 8 * cg]);
        ulonglong2 w23 = *reinterpret_cast<const ulonglong2*>(&ws[k * G3 + 8 * cg + 4]);
        ffma2(acc[0][0], xd0, w01.x); ffma2(acc[0][1], xd0, w01.y);
        ffma2(acc[0][2], xd0, w23.x); ffma2(acc[0][3], xd0, w23.y);
        ffma2(acc[1][0], xd1, w01.x); ffma2(acc[1][1], xd1, w01.y);
        ffma2(acc[1][2], xd1, w23.x); ffma2(acc[1][3], xd1, w23.y);
        ffma2(acc[2][0], xd2, w01.x); ffma2(acc[2][1], xd2, w01.y);
        ffma2(acc[2][2], xd2, w23.x); ffma2(acc[2][3], xd2, w23.y);
        ffma2(acc[3][0], xd3, w01.x); ffma2(acc[3][1], xd3, w01.y);
        ffma2(acc[3][2], xd3, w23.x); ffma2(acc[3][3], xd3, w23.y);
    }

    #pragma unroll
    for (int r = 0; r < 4; r++) {
        float* dst = &g_xw[(size_t)(row0 + 4 * rg + r) * G3 + 8 * cg];
        ulonglong2 v;
        v.x = fadd2(acc[r][0], bp[0]);
        v.y = fadd2(acc[r][1], bp[1]);
        *reinterpret_cast<ulonglong2*>(dst) = v;
        v.x = fadd2(acc[r][2], bp[2]);
        v.y = fadd2(acc[r][3], bp[3]);
        *reinterpret_cast<ulonglong2*>(dst + 4) = v;
    }
}

// ---------------------------------------------------------------------------
// Kernel 2: GRU scan + fused head — EXACT round-8 version (best measured:
// 956.7 us). 128 blocks x 384 threads, 4 batches/block; warp-level split-K
// (warp covers k-half w&1, lane owns 2 adjacent cols), weights 64 ull in regs,
// partials via gpart[2][4][384].
// ---------------------------------------------------------------------------
__global__ void __launch_bounds__(384, 1) gru_scan_kernel(
        const float* __restrict__ inputs,
        const float* __restrict__ Wh,
        const float* __restrict__ bias,
        const float* __restrict__ W_state,
        const float* __restrict__ w1,
        const float* __restrict__ b1,
        const float* __restrict__ gamma,
        const float* __restrict__ beta,
        const float* __restrict__ mean,
        const float* __restrict__ var,
        const float* __restrict__ w2,
        const float* __restrict__ b2,
        float* __restrict__ out) {
    __shared__ __align__(16) float hs[4][H_DIM];    // current h, 2 KB
    __shared__ float gpart[2][4][G3];               // recurrent partials, 12 KB
    __shared__ float red[4][64];                    // head partials

    const int t    = threadIdx.x;
    const int w    = t >> 5;
    const int lam  = t & 31;
    const int hb   = w & 1;                 // k-half of this warp
    const int kb   = hb * 64;
    const int col0 = (w >> 1) * 64 + lam * 2;   // col1 = col0 + 1
    const int b0   = blockIdx.x * 4;

    // activation-role indices (item1 for all threads, item2 for t<128)
    const int j1 = t & 127;
    const int ab = t >> 7;                  // activation batch, 0..2
    const float brz = bias[G3 + j1];
    const float brr = bias[G3 + 128 + j1];
    const float brh = bias[G3 + 256 + j1];

    // weights -> 64 packed ull (2 cols x 32 k-pairs)
    ull wc0[32], wc1[32];
    #pragma unroll
    for (int i = 0; i < 32; i++) {
        wc0[i] = packf2(__ldg(&Wh[(kb + 2 * i) * G3 + col0]),
                        __ldg(&Wh[(kb + 2 * i + 1) * G3 + col0]));
        wc1[i] = packf2(__ldg(&Wh[(kb + 2 * i) * G3 + col0 + 1]),
                        __ldg(&Wh[(kb + 2 * i + 1) * G3 + col0 + 1]));
    }

    for (int i = t; i < 4 * H_DIM; i += 384) (&hs[0][0])[i] = 0.f;
    const float* __restrict__ xw1 = g_xw + (size_t)(b0 + ab) * BSTRIDE + j1;
    const float* __restrict__ xw2 = g_xw + (size_t)(b0 + 3) * BSTRIDE + j1;  // t<128
    __syncthreads();

    for (int step = 0; step < T_DIM; step++) {
        const size_t so = (size_t)step * G3;
        // prefetch this step's input preacts for the activation phase
        float x1z = xw1[so], x1r = xw1[so + 128], x1h = xw1[so + 256];
        float x2z = 0.f, x2r = 0.f, x2h = 0.f;
        if (t < 128) { x2z = xw2[so]; x2r = xw2[so + 128]; x2h = xw2[so + 256]; }

        // GEMV over this warp's k-half for 2 columns x 4 batches
        ull a00 = 0ull, a01 = 0ull, a10 = 0ull, a11 = 0ull;
        ull a20 = 0ull, a21 = 0ull, a30 = 0ull, a31 = 0ull;
        #pragma unroll
        for (int k4 = 0; k4 < 16; k4++) {
            const int k = kb + 4 * k4;
            ulonglong2 h0 = *reinterpret_cast<const ulonglong2*>(&hs[0][k]);
            ffma2(a00, wc0[2 * k4], h0.x); ffma2(a00, wc0[2 * k4 + 1], h0.y);
            ffma2(a01, wc1[2 * k4], h0.x); ffma2(a01, wc1[2 * k4 + 1], h0.y);
            ulonglong2 h1 = *reinterpret_cast<const ulonglong2*>(&hs[1][k]);
            ffma2(a10, wc0[2 * k4], h1.x); ffma2(a10, wc0[2 * k4 + 1], h1.y);
            ffma2(a11, wc1[2 * k4], h1.x); ffma2(a11, wc1[2 * k4 + 1], h1.y);
            ulonglong2 h2 = *reinterpret_cast<const ulonglong2*>(&hs[2][k]);
            ffma2(a20, wc0[2 * k4], h2.x); ffma2(a20, wc0[2 * k4 + 1], h2.y);
            ffma2(a21, wc1[2 * k4], h2.x); ffma2(a21, wc1[2 * k4 + 1], h2.y);
            ulonglong2 h3 = *reinterpret_cast<const ulonglong2*>(&hs[3][k]);
            ffma2(a30, wc0[2 * k4], h3.x); ffma2(a30, wc0[2 * k4 + 1], h3.y);
            ffma2(a31, wc1[2 * k4], h3.x); ffma2(a31, wc1[2 * k4 + 1], h3.y);
        }
        {
            float2 s;
            s.x = ull_hsum(a00); s.y = ull_hsum(a01);
            *reinterpret_cast<float2*>(&gpart[hb][0][col0]) = s;
            s.x = ull_hsum(a10); s.y = ull_hsum(a11);
            *reinterpret_cast<float2*>(&gpart[hb][1][col0]) = s;
            s.x = ull_hsum(a20); s.y = ull_hsum(a21);
            *reinterpret_cast<float2*>(&gpart[hb][2][col0]) = s;
            s.x = ull_hsum(a30); s.y = ull_hsum(a31);
            *reinterpret_cast<float2*>(&gpart[hb][3][col0]) = s;
        }
        __syncthreads();

        // activation: item1 (all threads), item2 (t < 128, batch 3)
        {
            float z = fsigmoid(x1z + gpart[0][ab][j1] + gpart[1][ab][j1] + brz);
            float r = fsigmoid(x1r + gpart[0][ab][128 + j1] + gpart[1][ab][128 + j1] + brr);
            float hh = ftanh(x1h + r * (gpart[0][ab][256 + j1] + gpart[1][ab][256 + j1] + brh));
            hs[ab][j1] = z * hs[ab][j1] + (1.f - z) * hh;
        }
        if (t < 128) {
            float z = fsigmoid(x2z + gpart[0][3][j1] + gpart[1][3][j1] + brz);
            float r = fsigmoid(x2r + gpart[0][3][128 + j1] + gpart[1][3][128 + j1] + brr);
            float hh = ftanh(x2h + r * (gpart[0][3][256 + j1] + gpart[1][3][256 + j1] + brh));
            hs[3][j1] = z * hs[3][j1] + (1.f - z) * hh;
        }
        __syncthreads();
    }

    // ---- fused head: hidden += W_state[idx]; out = BN(relu(hid@w1+b1)) @ w2 + b2
    for (int i = t; i < 4 * H_DIM; i += 384) {
        int bb = i >> 7, j = i & 127;
        float st = inputs[((size_t)(b0 + bb) * T_DIM + (T_DIM - 1)) * 65 + 64];
        int idx = (int)st;
        idx = idx < 0 ? 0 : (idx > 2 ? 2 : idx);
        gpart[0][bb][j] = hs[bb][j] + W_state[idx * H_DIM + j];
    }
    __syncthreads();

    if (t < 256) {
        int bb = t >> 6, tt = t & 63;
        float a = b1[tt];
        #pragma unroll 8
        for (int k = 0; k < H_DIM; k++)
            a = fmaf(gpart[0][bb][k], w1[k * 64 + tt], a);
        a = fmaxf(a, 0.f);
        a = (a - mean[tt]) * rsqrtf(var[tt] + 1e-3f) * gamma[tt] + beta[tt];
        red[bb][tt] = a * w2[tt];
    }
    __syncthreads();

    if (t < 4) {
        float s = b2[0];
        #pragma unroll 8
        for (int k = 0; k < 64; k++) s += red[t][k];
        out[b0 + t] = s;
    }
}

// ---------------------------------------------------------------------------
extern "C" void kernel_launch(void* const* d_in, const int* in_sizes, int n_in,
                              void* d_out, int out_size) {
    const float* inputs  = (const float*)d_in[0];
    const float* Wx      = (const float*)d_in[1];
    const float* Wh      = (const float*)d_in[2];
    const float* bias    = (const float*)d_in[3];
    const float* W_state = (const float*)d_in[4];
    const float* w1      = (const float*)d_in[5];
    const float* b1      = (const float*)d_in[6];
    const float* gamma   = (const float*)d_in[7];
    const float* beta    = (const float*)d_in[8];
    const float* mean    = (const float*)d_in[9];
    const float* var     = (const float*)d_in[10];
    const float* w2      = (const float*)d_in[11];
    const float* b2      = (const float*)d_in[12];
    float* out = (float*)d_out;

    cudaFuncSetAttribute(xw_kernel,
                         cudaFuncAttributeMaxDynamicSharedMemorySize,
                         XW_SMEM_FLOATS * 4);

    xw_kernel<<<(B_DIM * T_DIM) / 64, XW_NTH, XW_SMEM_FLOATS * 4>>>(inputs, Wx, bias);
    gru_scan_kernel<<<B_DIM / 4, 384>>>(inputs, Wh, bias, W_state, w1, b1,
                                        gamma, beta, mean, var, w2, b2, out);
}

// round 11
// speedup vs baseline: 1.0712x; 1.0348x over previous
#include <cuda_runtime.h>
#include <cuda_bf16.h>
#include <cstring>

#define T_DIM 512
#define B_DIM 512
#define FDIM  64
#define H_DIM 128
#define G3    384   // 3*H
#define BSTRIDE ((size_t)T_DIM * G3)

// ---- scratch (device globals; no allocation) ----
__device__ float g_xw[(size_t)B_DIM * T_DIM * G3];   // x@Wx + b_in per (b,t)
// Wx split, column-major padded: [col][200] bf16: k0-63=whi, 64-127=wlo, 128-191=whi
__device__ unsigned int g_bp32[384 * 100];           // same storage viewed as b32 words

typedef unsigned long long ull;

__device__ __forceinline__ void ffma2(ull& d, ull a, ull b) {
    asm("fma.rn.f32x2 %0, %1, %2, %3;" : "=l"(d) : "l"(a), "l"(b), "l"(d));
}
__device__ __forceinline__ ull packf2(float lo, float hi) {
    ull u;
    asm("mov.b64 %0, {%1,%2};" : "=l"(u) : "f"(lo), "f"(hi));
    return u;
}
__device__ __forceinline__ float ull_hsum(ull u) {
    float lo, hi;
    asm("mov.b64 {%0,%1}, %2;" : "=f"(lo), "=f"(hi) : "l"(u));
    return lo + hi;
}
__device__ __forceinline__ float fsigmoid(float x) {
    return __fdividef(1.f, 1.f + __expf(-x));
}
__device__ __forceinline__ float ftanh(float x) {
    float e = __expf(2.f * x);
    return 1.f - __fdividef(2.f, e + 1.f);
}
__device__ __forceinline__ unsigned short bf_raw(__nv_bfloat16 h) {
    unsigned short r;
    memcpy(&r, &h, 2);
    return r;
}

// ---------------------------------------------------------------------------
// Kernel 0: split Wx into bf16 hi/lo, column-major padded [col][200].
// ---------------------------------------------------------------------------
__global__ void wprep_kernel(const float* __restrict__ Wx) {
    int col = blockIdx.x * 128 + threadIdx.x;   // grid 3 x 128
    unsigned short* p = (unsigned short*)g_bp32;
    for (int k = 0; k < FDIM; k++) {
        float v = Wx[k * G3 + col];
        __nv_bfloat16 h = __float2bfloat16(v);
        float lo = v - __bfloat162float(h);
        unsigned short hr = bf_raw(h);
        p[col * 200 + k]       = hr;                              // whi
        p[col * 200 + 64 + k]  = bf_raw(__float2bfloat16(lo));    // wlo
        p[col * 200 + 128 + k] = hr;                              // whi
    }
    for (int k = 192; k < 200; k++) p[col * 200 + k] = 0;
}

// ---------------------------------------------------------------------------
// Kernel 1: xw = x @ Wx + b_in via bf16 tensor cores (mma.sync m16n8k16),
// 2-term error split folded into K=192: A' = [xhi | xhi | xlo],
// B' = [whi ; wlo ; whi]  ->  xhi*whi + xhi*wlo + xlo*whi (err ~1e-5).
// Grid (6 n-groups, 2048 m-tiles); CTA tile 128 rows x 64 cols; 8 warps,
// warp = m16 x n64 (8 ntiles, 32 f32 acc regs). x converted to bf16 hi/lo
// in smem in-kernel; B' slab staged to smem. All smem fragment loads are
// bank-conflict-free by padding (A row stride 36 words, B col stride 100).
// ---------------------------------------------------------------------------
#define MM_NTH 256
#define MM_SMEM (2 * 128 * 72 * 2 + 64 * 200 * 2)   // hi + lo + B slab = 62464 B

extern __shared__ __align__(16) unsigned char smraw[];

__global__ void __launch_bounds__(MM_NTH, 1) xw_mma_kernel(const float* __restrict__ inputs,
                                                           const float* __restrict__ bias) {
    __nv_bfloat16* hiS = (__nv_bfloat16*)smraw;                    // [128][72]
    __nv_bfloat16* loS = hiS + 128 * 72;                           // [128][72]
    unsigned int*  bS32 = (unsigned int*)(loS + 128 * 72);         // [64][100] words

    const int t    = threadIdx.x;
    const int n0   = blockIdx.x * 64;
    const size_t row0 = (size_t)blockIdx.y * 128;

    // stage + convert x tile (128 rows x 64 k) into bf16 hi/lo
    for (int i = t; i < 128 * 64; i += MM_NTH) {
        int r = i >> 6, k = i & 63;
        float v = inputs[(row0 + r) * 65 + k];
        __nv_bfloat16 h = __float2bfloat16(v);
        hiS[r * 72 + k] = h;
        loS[r * 72 + k] = __float2bfloat16(v - __bfloat162float(h));
    }
    // stage B' slab (64 cols x 100 words)
    for (int i = t; i < 64 * 100; i += MM_NTH) {
        int c = i / 100, kw = i - c * 100;
        bS32[c * 100 + kw] = g_bp32[(size_t)(n0 + c) * 100 + kw];
    }
    __syncthreads();

    const int w    = t >> 5;
    const int lane = t & 31;
    const int g    = lane >> 2;
    const int tq   = lane & 3;
    const int arow = w * 16 + g;          // rows arow, arow+8 of the tile
    const unsigned int* hi32 = (const unsigned int*)hiS;   // row stride 36 words
    const unsigned int* lo32 = (const unsigned int*)loS;

    float acc[8][4];
    #pragma unroll
    for (int nt = 0; nt < 8; nt++)
        #pragma unroll
        for (int m = 0; m < 4; m++) acc[nt][m] = 0.f;

    #pragma unroll
    for (int c = 0; c < 12; c++) {
        const unsigned int* asrc = (c < 8) ? hi32 : lo32;
        const int koff  = (c & 3) * 8;    // words within the 64-k tile
        const int bkoff = c * 8;          // words within the 192-k B column
        unsigned int a0 = asrc[(arow)     * 36 + koff + tq];
        unsigned int a1 = asrc[(arow + 8) * 36 + koff + tq];
        unsigned int a2 = asrc[(arow)     * 36 + koff + 4 + tq];
        unsigned int a3 = asrc[(arow + 8) * 36 + koff + 4 + tq];
        #pragma unroll
        for (int nt = 0; nt < 8; nt++) {
            unsigned int b0 = bS32[(nt * 8 + g) * 100 + bkoff + tq];
            unsigned int b1 = bS32[(nt * 8 + g) * 100 + bkoff + 4 + tq];
            asm("mma.sync.aligned.m16n8k16.row.col.f32.bf16.bf16.f32 "
                "{%0,%1,%2,%3}, {%4,%5,%6,%7}, {%8,%9}, {%0,%1,%2,%3};"
                : "+f"(acc[nt][0]), "+f"(acc[nt][1]), "+f"(acc[nt][2]), "+f"(acc[nt][3])
                : "r"(a0), "r"(a1), "r"(a2), "r"(a3), "r"(b0), "r"(b1));
        }
    }

    // epilogue: add bias, write fp32
    #pragma unroll
    for (int nt = 0; nt < 8; nt++) {
        int col = n0 + nt * 8 + 2 * tq;
        float2 bv = *(const float2*)&bias[col];
        float2 v0; v0.x = acc[nt][0] + bv.x; v0.y = acc[nt][1] + bv.y;
        float2 v1; v1.x = acc[nt][2] + bv.x; v1.y = acc[nt][3] + bv.y;
        *(float2*)&g_xw[(row0 + arow) * G3 + col]     = v0;
        *(float2*)&g_xw[(row0 + arow + 8) * G3 + col] = v1;
    }
}

// ---------------------------------------------------------------------------
// Kernel 2: GRU scan + fused head — EXACT round-8/10 version (961 us, 88% of
// the corrected fp32 ceiling). Unchanged for attribution.
// ---------------------------------------------------------------------------
__global__ void __launch_bounds__(384, 1) gru_scan_kernel(
        const float* __restrict__ inputs,
        const float* __restrict__ Wh,
        const float* __restrict__ bias,
        const float* __restrict__ W_state,
        const float* __restrict__ w1,
        const float* __restrict__ b1,
        const float* __restrict__ gamma,
        const float* __restrict__ beta,
        const float* __restrict__ mean,
        const float* __restrict__ var,
        const float* __restrict__ w2,
        const float* __restrict__ b2,
        float* __restrict__ out) {
    __shared__ __align__(16) float hs[4][H_DIM];
    __shared__ float gpart[2][4][G3];
    __shared__ float red[4][64];

    const int t    = threadIdx.x;
    const int w    = t >> 5;
    const int lam  = t & 31;
    const int hb   = w & 1;
    const int kb   = hb * 64;
    const int col0 = (w >> 1) * 64 + lam * 2;
    const int b0   = blockIdx.x * 4;

    const int j1 = t & 127;
    const int ab = t >> 7;
    const float brz = bias[G3 + j1];
    const float brr = bias[G3 + 128 + j1];
    const float brh = bias[G3 + 256 + j1];

    ull wc0[32], wc1[32];
    #pragma unroll
    for (int i = 0; i < 32; i++) {
        wc0[i] = packf2(__ldg(&Wh[(kb + 2 * i) * G3 + col0]),
                        __ldg(&Wh[(kb + 2 * i + 1) * G3 + col0]));
        wc1[i] = packf2(__ldg(&Wh[(kb + 2 * i) * G3 + col0 + 1]),
                        __ldg(&Wh[(kb + 2 * i + 1) * G3 + col0 + 1]));
    }

    for (int i = t; i < 4 * H_DIM; i += 384) (&hs[0][0])[i] = 0.f;
    const float* __restrict__ xw1 = g_xw + (size_t)(b0 + ab) * BSTRIDE + j1;
    const float* __restrict__ xw2 = g_xw + (size_t)(b0 + 3) * BSTRIDE + j1;
    __syncthreads();

    for (int step = 0; step < T_DIM; step++) {
        const size_t so = (size_t)step * G3;
        float x1z = xw1[so], x1r = xw1[so + 128], x1h = xw1[so + 256];
        float x2z = 0.f, x2r = 0.f, x2h = 0.f;
        if (t < 128) { x2z = xw2[so]; x2r = xw2[so + 128]; x2h = xw2[so + 256]; }

        ull a00 = 0ull, a01 = 0ull, a10 = 0ull, a11 = 0ull;
        ull a20 = 0ull, a21 = 0ull, a30 = 0ull, a31 = 0ull;
        #pragma unroll
        for (int k4 = 0; k4 < 16; k4++) {
            const int k = kb + 4 * k4;
            ulonglong2 h0 = *reinterpret_cast<const ulonglong2*>(&hs[0][k]);
            ffma2(a00, wc0[2 * k4], h0.x); ffma2(a00, wc0[2 * k4 + 1], h0.y);
            ffma2(a01, wc1[2 * k4], h0.x); ffma2(a01, wc1[2 * k4 + 1], h0.y);
            ulonglong2 h1 = *reinterpret_cast<const ulonglong2*>(&hs[1][k]);
            ffma2(a10, wc0[2 * k4], h1.x); ffma2(a10, wc0[2 * k4 + 1], h1.y);
            ffma2(a11, wc1[2 * k4], h1.x); ffma2(a11, wc1[2 * k4 + 1], h1.y);
            ulonglong2 h2 = *reinterpret_cast<const ulonglong2*>(&hs[2][k]);
            ffma2(a20, wc0[2 * k4], h2.x); ffma2(a20, wc0[2 * k4 + 1], h2.y);
            ffma2(a21, wc1[2 * k4], h2.x); ffma2(a21, wc1[2 * k4 + 1], h2.y);
            ulonglong2 h3 = *reinterpret_cast<const ulonglong2*>(&hs[3][k]);
            ffma2(a30, wc0[2 * k4], h3.x); ffma2(a30, wc0[2 * k4 + 1], h3.y);
            ffma2(a31, wc1[2 * k4], h3.x); ffma2(a31, wc1[2 * k4 + 1], h3.y);
        }
        {
            float2 s;
            s.x = ull_hsum(a00); s.y = ull_hsum(a01);
            *reinterpret_cast<float2*>(&gpart[hb][0][col0]) = s;
            s.x = ull_hsum(a10); s.y = ull_hsum(a11);
            *reinterpret_cast<float2*>(&gpart[hb][1][col0]) = s;
            s.x = ull_hsum(a20); s.y = ull_hsum(a21);
            *reinterpret_cast<float2*>(&gpart[hb][2][col0]) = s;
            s.x = ull_hsum(a30); s.y = ull_hsum(a31);
            *reinterpret_cast<float2*>(&gpart[hb][3][col0]) = s;
        }
        __syncthreads();

        {
            float z = fsigmoid(x1z + gpart[0][ab][j1] + gpart[1][ab][j1] + brz);
            float r = fsigmoid(x1r + gpart[0][ab][128 + j1] + gpart[1][ab][128 + j1] + brr);
            float hh = ftanh(x1h + r * (gpart[0][ab][256 + j1] + gpart[1][ab][256 + j1] + brh));
            hs[ab][j1] = z * hs[ab][j1] + (1.f - z) * hh;
        }
        if (t < 128) {
            float z = fsigmoid(x2z + gpart[0][3][j1] + gpart[1][3][j1] + brz);
            float r = fsigmoid(x2r + gpart[0][3][128 + j1] + gpart[1][3][128 + j1] + brr);
            float hh = ftanh(x2h + r * (gpart[0][3][256 + j1] + gpart[1][3][256 + j1] + brh));
            hs[3][j1] = z * hs[3][j1] + (1.f - z) * hh;
        }
        __syncthreads();
    }

    for (int i = t; i < 4 * H_DIM; i += 384) {
        int bb = i >> 7, j = i & 127;
        float st = inputs[((size_t)(b0 + bb) * T_DIM + (T_DIM - 1)) * 65 + 64];
        int idx = (int)st;
        idx = idx < 0 ? 0 : (idx > 2 ? 2 : idx);
        gpart[0][bb][j] = hs[bb][j] + W_state[idx * H_DIM + j];
    }
    __syncthreads();

    if (t < 256) {
        int bb = t >> 6, tt = t & 63;
        float a = b1[tt];
        #pragma unroll 8
        for (int k = 0; k < H_DIM; k++)
            a = fmaf(gpart[0][bb][k], w1[k * 64 + tt], a);
        a = fmaxf(a, 0.f);
        a = (a - mean[tt]) * rsqrtf(var[tt] + 1e-3f) * gamma[tt] + beta[tt];
        red[bb][tt] = a * w2[tt];
    }
    __syncthreads();

    if (t < 4) {
        float s = b2[0];
        #pragma unroll 8
        for (int k = 0; k < 64; k++) s += red[t][k];
        out[b0 + t] = s;
    }
}

// ---------------------------------------------------------------------------
extern "C" void kernel_launch(void* const* d_in, const int* in_sizes, int n_in,
                              void* d_out, int out_size) {
    const float* inputs  = (const float*)d_in[0];
    const float* Wx      = (const float*)d_in[1];
    const float* Wh      = (const float*)d_in[2];
    const float* bias    = (const float*)d_in[3];
    const float* W_state = (const float*)d_in[4];
    const float* w1      = (const float*)d_in[5];
    const float* b1      = (const float*)d_in[6];
    const float* gamma   = (const float*)d_in[7];
    const float* beta    = (const float*)d_in[8];
    const float* mean    = (const float*)d_in[9];
    const float* var     = (const float*)d_in[10];
    const float* w2      = (const float*)d_in[11];
    const float* b2      = (const float*)d_in[12];
    float* out = (float*)d_out;

    cudaFuncSetAttribute(xw_mma_kernel,
                         cudaFuncAttributeMaxDynamicSharedMemorySize, MM_SMEM);

    wprep_kernel<<<3, 128>>>(Wx);
    dim3 gg(6, (B_DIM * T_DIM) / 128);
    xw_mma_kernel<<<gg, MM_NTH, MM_SMEM>>>(inputs, bias);
    gru_scan_kernel<<<B_DIM / 4, 384>>>(inputs, Wh, bias, W_state, w1, b1,
                                        gamma, beta, mean, var, w2, b2, out);
}